// round 17
// baseline (speedup 1.0000x reference)
#include <cuda_runtime.h>
#include <cuda_fp16.h>
#include <math.h>
#include <stdint.h>

#define BB 2
#define SS 1024
#define EE 512
#define HH 64
#define DKK 8
#define FF 2048
#define BS (BB*SS)   // 2048

// ---- scratch (device globals: allocation-free) ----
__device__ float   g_q[BB*HH*SS*DKK];    // [B][H][S][8]
__device__ __half  g_attn_h[BS*EE];      // attention out (fp16)
__device__ float   g_x1[BS*EE];          // post-LN1 (f32, ffn2 residual)
__device__ __half  g_qf_h[BS*EE];        // cos(x1)*cos(theta) (fp16)
__device__ __half  g_hdn_h[BS*FF];       // FFN hidden (fp16)
__device__ float   g_pre2[2*BS*EE];      // split-K partials (2 x 4MB)
// pre-packed fp16 weights, k-pair layout: Wh[kk][n] = (W[2kk][n], W[2kk+1][n])
__device__ __half2 g_wch[(EE/2)*EE];     // 256x512
__device__ __half2 g_w1h[(EE/2)*FF];     // 256x2048
__device__ __half2 g_w2h[(FF/2)*EE];     // 1024x512

__device__ __forceinline__ float ex2a(float x) {
    float r; asm("ex2.approx.f32 %0, %1;" : "=f"(r) : "f"(x)); return r;
}
__device__ __forceinline__ void mma_tf32u(float& c0, float& c1, float& c2, float& c3,
                                          uint32_t A0, uint32_t A1, uint32_t A2, uint32_t A3,
                                          uint32_t B0, uint32_t B1) {
    asm volatile(
        "mma.sync.aligned.m16n8k8.row.col.f32.tf32.tf32.f32 "
        "{%0,%1,%2,%3},{%4,%5,%6,%7},{%8,%9},{%0,%1,%2,%3};"
        : "+f"(c0), "+f"(c1), "+f"(c2), "+f"(c3)
        : "r"(A0), "r"(A1), "r"(A2), "r"(A3), "r"(B0), "r"(B1));
}
__device__ __forceinline__ void mma_f16(float* acc,
                                        uint32_t a0, uint32_t a1, uint32_t a2, uint32_t a3,
                                        uint32_t b0, uint32_t b1) {
    asm volatile(
        "mma.sync.aligned.m16n8k16.row.col.f32.f16.f16.f32 "
        "{%0,%1,%2,%3},{%4,%5,%6,%7},{%8,%9},{%0,%1,%2,%3};"
        : "+f"(acc[0]), "+f"(acc[1]), "+f"(acc[2]), "+f"(acc[3])
        : "r"(a0), "r"(a1), "r"(a2), "r"(a3), "r"(b0), "r"(b1));
}
__device__ __forceinline__ uint32_t pack_h2(float lo, float hi) {
    __half2 h = __floats2half2_rn(lo, hi);
    return *reinterpret_cast<uint32_t*>(&h);
}

// =====================================================================
// K0: merged prep — qkv (first 512 blocks) + weight pre-pack (rest)
// =====================================================================
#define WC_E ((EE/2)*EE)     // 131072
#define W1_E ((EE/2)*FF)     // 524288
#define W2_E ((FF/2)*EE)     // 524288
#define QKV_BLOCKS 512
#define WPACK_BLOCKS ((WC_E + W1_E + W2_E) / 256)   // 4608

__global__ void prep_kernel(const float* __restrict__ x,
                            const float* __restrict__ theta,
                            const float* __restrict__ wc,
                            const float* __restrict__ w1,
                            const float* __restrict__ w2) {
    if (blockIdx.x < QKV_BLOCKS) {
        int i = blockIdx.x * 256 + threadIdx.x;   // over B*S*H
        int h  = i & (HH-1);
        int bs = i >> 6;
        const float* xp = x + bs*EE + h*DKK;
        float4 xa = *(const float4*)xp;
        float4 xb = *(const float4*)(xp + 4);
        float c0 = __cosf(xa.x + theta[0]);
        float c1 = __cosf(xa.y + theta[1]);
        float c2 = __cosf(xa.z + theta[2]);
        float c3 = __cosf(xa.w + theta[3]);
        float c4 = __cosf(xb.x + theta[4]);
        float c5 = __cosf(xb.y + theta[5]);
        float c6 = __cosf(xb.z + theta[6]);
        float c7 = __cosf(xb.w + theta[7]);
        float o1 = c0*c1;
        float o2 = o1*c2;
        float o3 = o2*c3;
        float o4 = o3*c4;
        float o5 = o4*c5;
        float o6 = o5*c6;
        float o7 = o6*c7;
        float o0 = c1*c2*c3*c4*c5*c6*c7;
        int b = bs >> 10, s = bs & (SS-1);
        float* qp = g_q + (((b*HH + h)*SS) + s)*DKK;
        *(float4*)qp       = make_float4(o0, o1, o2, o3);
        *(float4*)(qp + 4) = make_float4(o4, o5, o6, o7);
    } else {
        int i = (blockIdx.x - QKV_BLOCKS) * 256 + threadIdx.x;
        if (i < WC_E) {
            int kk = i >> 9, n = i & 511;
            g_wch[i] = __floats2half2_rn(wc[(2*kk)*EE + n], wc[(2*kk+1)*EE + n]);
        } else if (i < WC_E + W1_E) {
            int j = i - WC_E;
            int kk = j >> 11, n = j & 2047;
            g_w1h[j] = __floats2half2_rn(w1[(2*kk)*FF + n], w1[(2*kk+1)*FF + n]);
        } else {
            int j = i - WC_E - W1_E;
            int kk = j >> 9, n = j & 511;
            g_w2h[j] = __floats2half2_rn(w2[(2*kk)*EE + n], w2[(2*kk+1)*EE + n]);
        }
    }
}

// =====================================================================
// K2: tensor-core attention (validated R10/R14 form, fp16 epilogue)
// =====================================================================
__global__ void __launch_bounds__(256, 4) attn_mma_kernel() {
    __shared__ float Ks[SS*12];
    const int bh   = blockIdx.x >> 3;
    const int tile = blockIdx.x & 7;

    const float* qsrc = g_q + bh*(SS*DKK);
    for (int j = threadIdx.x; j < SS*DKK/4; j += 256) {
        float4 v = ((const float4*)qsrc)[j];
        int t = j >> 1, hf = (j & 1) * 4;
        *(float4*)&Ks[t*12 + hf] = v;
    }
    __syncthreads();

    const int lane = threadIdx.x & 31, warp = threadIdx.x >> 5;
    const int g = lane >> 2, tc = lane & 3;
    const int sg = (g >> 1) + (g & 1)*4;
    const int row0 = tile*128 + warp*16;

    const float SCL = 0.35355339059f * 1.44269504089f;
    const uint32_t qa0 = __float_as_uint(Ks[(row0+g  )*12 + tc  ] * SCL);
    const uint32_t qa1 = __float_as_uint(Ks[(row0+g+8)*12 + tc  ] * SCL);
    const uint32_t qa2 = __float_as_uint(Ks[(row0+g  )*12 + tc+4] * SCL);
    const uint32_t qa3 = __float_as_uint(Ks[(row0+g+8)*12 + tc+4] * SCL);

    float oa0=0.f, oa1=0.f, oa2=0.f, oa3=0.f;
    float ob0=0.f, ob1=0.f, ob2=0.f, ob3=0.f;
    float ra0=0.f, ra1=0.f, rb0=0.f, rb1=0.f;

    #pragma unroll 2
    for (int t0 = 0; t0 < SS; t0 += 16) {
        const int tA = t0, tB = t0 + 8;
        uint32_t sA0 = __float_as_uint(Ks[(tA+sg)*12 + tc  ]);
        uint32_t sA1 = __float_as_uint(Ks[(tA+sg)*12 + tc+4]);
        uint32_t sB0 = __float_as_uint(Ks[(tB+sg)*12 + tc  ]);
        uint32_t sB1 = __float_as_uint(Ks[(tB+sg)*12 + tc+4]);
        float a0=0.f,a1=0.f,a2=0.f,a3=0.f;
        float b0=0.f,b1=0.f,b2=0.f,b3=0.f;
        mma_tf32u(a0,a1,a2,a3, qa0,qa1,qa2,qa3, sA0,sA1);
        mma_tf32u(b0,b1,b2,b3, qa0,qa1,qa2,qa3, sB0,sB1);

        float pA0 = ex2a(a0), pA1 = ex2a(a1), pA2 = ex2a(a2), pA3 = ex2a(a3);
        float pB0 = ex2a(b0), pB1 = ex2a(b1), pB2 = ex2a(b2), pB3 = ex2a(b3);
        ra0 += pA0 + pA1;  ra1 += pA2 + pA3;
        rb0 += pB0 + pB1;  rb1 += pB2 + pB3;

        uint32_t vA0 = __float_as_uint(Ks[(tA+tc  )*12 + g]);
        uint32_t vA1 = __float_as_uint(Ks[(tA+tc+4)*12 + g]);
        uint32_t vB0 = __float_as_uint(Ks[(tB+tc  )*12 + g]);
        uint32_t vB1 = __float_as_uint(Ks[(tB+tc+4)*12 + g]);
        mma_tf32u(oa0,oa1,oa2,oa3,
                  __float_as_uint(pA0), __float_as_uint(pA2),
                  __float_as_uint(pA1), __float_as_uint(pA3), vA0, vA1);
        mma_tf32u(ob0,ob1,ob2,ob3,
                  __float_as_uint(pB0), __float_as_uint(pB2),
                  __float_as_uint(pB1), __float_as_uint(pB3), vB0, vB1);
    }

    float rs0 = ra0 + rb0, rs1 = ra1 + rb1;
    rs0 += __shfl_xor_sync(0xffffffffu, rs0, 1);
    rs0 += __shfl_xor_sync(0xffffffffu, rs0, 2);
    rs1 += __shfl_xor_sync(0xffffffffu, rs1, 1);
    rs1 += __shfl_xor_sync(0xffffffffu, rs1, 2);
    float i0 = 1.0f / rs0, i1 = 1.0f / rs1;

    const int b = bh >> 6, h = bh & (HH-1);
    const int r0 = row0 + g, r1 = r0 + 8;
    *reinterpret_cast<uint32_t*>(g_attn_h + (b*SS + r0)*EE + h*DKK + 2*tc)
        = pack_h2((oa0+ob0)*i0, (oa1+ob1)*i0);
    *reinterpret_cast<uint32_t*>(g_attn_h + (b*SS + r1)*EE + h*DKK + 2*tc)
        = pack_h2((oa2+ob2)*i1, (oa3+ob3)*i1);
}

// =====================================================================
// Unified fp16 GEMM, depth-2 register prefetch (ping-pong, unroll 2).
// KCH = K per split. PARTIAL: raw f32 split output; else bias(+relu) fp16.
// =====================================================================
template<int KCH, bool PARTIAL, bool RELU>
__global__ void __launch_bounds__(256, 3) mma_gemm_kernel(
    const __half* __restrict__ A, const __half2* __restrict__ Wh,
    const float* __restrict__ bias,
    float* __restrict__ partial, __half* __restrict__ outh, int N, int KTOT)
{
    __shared__ __half As[32][40];
    __shared__ __half2 Bs[16][136];

    const int rowbase = blockIdx.y * 32;
    const int colbase = blockIdx.x * 128;
    const int ks      = blockIdx.z;
    const int tid  = threadIdx.x;
    const int warp = tid >> 5, lane = tid & 31;
    const int wm = warp >> 2;
    const int wn = warp & 3;
    const int g  = lane >> 2, tc = lane & 3;

    const __half2* Wp = Wh + (ks * (KCH/2)) * N;
    float* outp = PARTIAL ? (partial + ks * (BS * N)) : nullptr;

    float acc[4][4];
    #pragma unroll
    for (int i = 0; i < 4; i++)
        #pragma unroll
        for (int j = 0; j < 4; j++) acc[i][j] = 0.f;

    const int arow = tid >> 3, ak = (tid & 7) * 4;
    const __half* Aptr = A + (rowbase + arow) * KTOT + ks * KCH + ak;
    const int blin_kk = tid >> 6;
    const int blin_u2 = (tid & 63) * 2;

    const int NCHUNK = KCH / 32;
    uint2 aR[2]; uint2 bR[2][4];
    #pragma unroll
    for (int p = 0; p < 2; p++) {
        aR[p] = *(const uint2*)(Aptr + p*32);
        #pragma unroll
        for (int i = 0; i < 4; i++) {
            int kk = p*16 + blin_kk + i*4;
            bR[p][i] = *(const uint2*)(Wp + kk * N + colbase + blin_u2);
        }
    }

    #pragma unroll 2
    for (int ch = 0; ch < NCHUNK; ch++) {
        const int s2 = ch & 1;
        __syncthreads();
        *reinterpret_cast<uint2*>(&As[arow][ak]) = aR[s2];
        #pragma unroll
        for (int i = 0; i < 4; i++) {
            int kk = blin_kk + i*4;
            *reinterpret_cast<uint2*>(&Bs[kk][blin_u2]) = bR[s2][i];
        }
        __syncthreads();

        if (ch + 2 < NCHUNK) {
            aR[s2] = *(const uint2*)(Aptr + (ch+2)*32);
            #pragma unroll
            for (int i = 0; i < 4; i++) {
                int kk = (ch+2)*16 + blin_kk + i*4;
                bR[s2][i] = *(const uint2*)(Wp + kk * N + colbase + blin_u2);
            }
        }

        #pragma unroll
        for (int s = 0; s < 2; s++) {
            const int kc = s*16 + 2*tc;
            uint32_t a0 = *reinterpret_cast<const uint32_t*>(&As[wm*16 + g    ][kc    ]);
            uint32_t a1 = *reinterpret_cast<const uint32_t*>(&As[wm*16 + g + 8][kc    ]);
            uint32_t a2 = *reinterpret_cast<const uint32_t*>(&As[wm*16 + g    ][kc + 8]);
            uint32_t a3 = *reinterpret_cast<const uint32_t*>(&As[wm*16 + g + 8][kc + 8]);
            #pragma unroll
            for (int nt = 0; nt < 4; nt++) {
                int col = wn*32 + nt*8 + g;
                uint32_t b0 = *reinterpret_cast<const uint32_t*>(&Bs[s*8 + tc    ][col]);
                uint32_t b1 = *reinterpret_cast<const uint32_t*>(&Bs[s*8 + tc + 4][col]);
                mma_f16(acc[nt], a0, a1, a2, a3, b0, b1);
            }
        }
    }

    #pragma unroll
    for (int nt = 0; nt < 4; nt++) {
        int col = colbase + wn*32 + nt*8 + 2*tc;
        int r0 = rowbase + wm*16 + g;
        int r1 = r0 + 8;
        if (PARTIAL) {
            *(float2*)(outp + r0*N + col) = make_float2(acc[nt][0], acc[nt][1]);
            *(float2*)(outp + r1*N + col) = make_float2(acc[nt][2], acc[nt][3]);
        } else {
            float bx = bias[col], by = bias[col+1];
            float v00 = acc[nt][0] + bx, v01 = acc[nt][1] + by;
            float v10 = acc[nt][2] + bx, v11 = acc[nt][3] + by;
            if (RELU) {
                v00 = fmaxf(v00, 0.f); v01 = fmaxf(v01, 0.f);
                v10 = fmaxf(v10, 0.f); v11 = fmaxf(v11, 0.f);
            }
            *reinterpret_cast<uint32_t*>(outh + r0*N + col) = pack_h2(v00, v01);
            *reinterpret_cast<uint32_t*>(outh + r1*N + col) = pack_h2(v10, v11);
        }
    }
}

// =====================================================================
// LN kernels: sum 2 split-K partials + bias + residual, then LN
// =====================================================================
__global__ void __launch_bounds__(128) ln1_cos_kernel(
    const float* __restrict__ part, const float* __restrict__ bias,
    const float* __restrict__ x,
    const float* __restrict__ w,  const float* __restrict__ b,
    const float* __restrict__ thf)
{
    __shared__ float sS[4], sQ[4];
    const int row = blockIdx.x;
    const int t = threadIdx.x;
    float4 p0 = ((const float4*)(part + 0*BS*EE + row*EE))[t];
    float4 p1 = ((const float4*)(part + 1*BS*EE + row*EE))[t];
    float4 bb = ((const float4*)bias)[t];
    float4 xv = ((const float4*)(x + row*EE))[t];
    float4 v;
    v.x = (p0.x + p1.x) + bb.x + xv.x;
    v.y = (p0.y + p1.y) + bb.y + xv.y;
    v.z = (p0.z + p1.z) + bb.z + xv.z;
    v.w = (p0.w + p1.w) + bb.w + xv.w;
    float s = v.x + v.y + v.z + v.w;
    float q = v.x*v.x + v.y*v.y + v.z*v.z + v.w*v.w;
    #pragma unroll
    for (int o = 16; o; o >>= 1) {
        s += __shfl_xor_sync(0xffffffffu, s, o);
        q += __shfl_xor_sync(0xffffffffu, q, o);
    }
    if ((t & 31) == 0) { sS[t>>5] = s; sQ[t>>5] = q; }
    __syncthreads();
    s = sS[0] + sS[1] + sS[2] + sS[3];
    q = sQ[0] + sQ[1] + sQ[2] + sQ[3];
    float mu   = s * (1.0f/EE);
    float var  = q * (1.0f/EE) - mu*mu;
    float rstd = rsqrtf(var + 1e-5f);
    float4 lw = ((const float4*)w)[t];
    float4 lb = ((const float4*)b)[t];
    float4 th = ((const float4*)thf)[t];
    float4 x1;
    x1.x = (v.x - mu)*rstd*lw.x + lb.x;
    x1.y = (v.y - mu)*rstd*lw.y + lb.y;
    x1.z = (v.z - mu)*rstd*lw.z + lb.z;
    x1.w = (v.w - mu)*rstd*lw.w + lb.w;
    ((float4*)(g_x1 + row*EE))[t] = x1;
    float qx = __cosf(x1.x)*__cosf(th.x);
    float qy = __cosf(x1.y)*__cosf(th.y);
    float qz = __cosf(x1.z)*__cosf(th.z);
    float qw = __cosf(x1.w)*__cosf(th.w);
    *reinterpret_cast<uint2*>(g_qf_h + row*EE + t*4) =
        make_uint2(pack_h2(qx, qy), pack_h2(qz, qw));
}

__global__ void __launch_bounds__(128) ln2_kernel(
    const float* __restrict__ part, const float* __restrict__ bias,
    const float* __restrict__ res,
    const float* __restrict__ w,  const float* __restrict__ b,
    float* __restrict__ out)
{
    __shared__ float sS[4], sQ[4];
    const int row = blockIdx.x;
    const int t = threadIdx.x;
    float4 p0 = ((const float4*)(part + 0*BS*EE + row*EE))[t];
    float4 p1 = ((const float4*)(part + 1*BS*EE + row*EE))[t];
    float4 bb = ((const float4*)bias)[t];
    float4 rv = ((const float4*)(res + row*EE))[t];
    float4 v;
    v.x = (p0.x + p1.x) + bb.x + rv.x;
    v.y = (p0.y + p1.y) + bb.y + rv.y;
    v.z = (p0.z + p1.z) + bb.z + rv.z;
    v.w = (p0.w + p1.w) + bb.w + rv.w;
    float s = v.x + v.y + v.z + v.w;
    float q = v.x*v.x + v.y*v.y + v.z*v.z + v.w*v.w;
    #pragma unroll
    for (int o = 16; o; o >>= 1) {
        s += __shfl_xor_sync(0xffffffffu, s, o);
        q += __shfl_xor_sync(0xffffffffu, q, o);
    }
    if ((t & 31) == 0) { sS[t>>5] = s; sQ[t>>5] = q; }
    __syncthreads();
    s = sS[0] + sS[1] + sS[2] + sS[3];
    q = sQ[0] + sQ[1] + sQ[2] + sQ[3];
    float mu   = s * (1.0f/EE);
    float var  = q * (1.0f/EE) - mu*mu;
    float rstd = rsqrtf(var + 1e-5f);
    float4 lw = ((const float4*)w)[t];
    float4 lb = ((const float4*)b)[t];
    float4 o4;
    o4.x = (v.x - mu)*rstd*lw.x + lb.x;
    o4.y = (v.y - mu)*rstd*lw.y + lb.y;
    o4.z = (v.z - mu)*rstd*lw.z + lb.z;
    o4.w = (v.w - mu)*rstd*lw.w + lb.w;
    ((float4*)(out + row*EE))[t] = o4;
}

// =====================================================================
extern "C" void kernel_launch(void* const* d_in, const int* in_sizes, int n_in,
                              void* d_out, int out_size) {
    const float* x         = (const float*)d_in[0];
    const float* theta_at  = (const float*)d_in[1];
    const float* w_combine = (const float*)d_in[2];
    const float* b_combine = (const float*)d_in[3];
    const float* theta_ffn = (const float*)d_in[4];
    const float* w1        = (const float*)d_in[5];
    const float* b1        = (const float*)d_in[6];
    const float* w2        = (const float*)d_in[7];
    const float* b2        = (const float*)d_in[8];
    const float* ln1w      = (const float*)d_in[9];
    const float* ln1b      = (const float*)d_in[10];
    const float* ln2w      = (const float*)d_in[11];
    const float* ln2b      = (const float*)d_in[12];
    float* out = (float*)d_out;

    __half* d_attn_h; cudaGetSymbolAddress((void**)&d_attn_h, g_attn_h);
    float*  d_x1;     cudaGetSymbolAddress((void**)&d_x1,     g_x1);
    __half* d_qf_h;   cudaGetSymbolAddress((void**)&d_qf_h,   g_qf_h);
    __half* d_hdn_h;  cudaGetSymbolAddress((void**)&d_hdn_h,  g_hdn_h);
    float*  d_pre2;   cudaGetSymbolAddress((void**)&d_pre2,   g_pre2);
    __half2* d_wch;   cudaGetSymbolAddress((void**)&d_wch,    g_wch);
    __half2* d_w1h;   cudaGetSymbolAddress((void**)&d_w1h,    g_w1h);
    __half2* d_w2h;   cudaGetSymbolAddress((void**)&d_w2h,    g_w2h);

    prep_kernel<<<QKV_BLOCKS + WPACK_BLOCKS, 256>>>(x, theta_at,
                                                    w_combine, w1, w2);
    attn_mma_kernel<<<1024, 256>>>();

    // combine: split-K x2 (KCH=256) -> g_pre2 (512 CTAs = one wave)
    mma_gemm_kernel<256, true, false><<<dim3(4, 64, 2), 256>>>(
        d_attn_h, d_wch, nullptr, d_pre2, nullptr, EE, EE);
    ln1_cos_kernel<<<BS, 128>>>(d_pre2, b_combine, x, ln1w, ln1b, theta_ffn);

    // ffn1: K=512 full, depth-2 prefetch, bias+relu -> fp16
    mma_gemm_kernel<512, false, true><<<dim3(16, 64, 1), 256>>>(
        d_qf_h, d_w1h, b1, nullptr, d_hdn_h, FF, EE);

    // ffn2: split-K x2 (KCH=1024) -> g_pre2 (512 CTAs = one wave)
    mma_gemm_kernel<1024, true, false><<<dim3(4, 64, 2), 256>>>(
        d_hdn_h, d_w2h, nullptr, d_pre2, nullptr, EE, FF);
    ln2_kernel<<<BS, 128>>>(d_pre2, b2, d_x1, ln2w, ln2b, out);
}